// round 14
// baseline (speedup 1.0000x reference)
#include <cuda_runtime.h>
#include <math.h>

#define B_    1024
#define V_    64
#define L1_   6
#define D_    512
#define NROWS 1152   // V * 3 * 6 distinct (var, cat, lag) combos
#define NEMB  73     // 64 var + 3 strength + 6 lag partial-GEMM rows
#define KCH   8      // k-split chunks for the embedding GEMM
#define KSP   4      // k-split for the table GEMM

// Static scratch (no allocations allowed)
__device__ float g_rowsP[KCH * NEMB * D_];  // k-split partials of emb @ W1
__device__ float g_Tpre[NROWS * D_];        // relu(...) rows
__device__ float g_Tp[KSP * NROWS * D_];    // table GEMM k-partials
__device__ float g_T[NROWS * D_];           // final row table
__device__ int   g_idx[B_ * V_];            // per (b,v) combo index

typedef unsigned long long ull;
__device__ __forceinline__ void ffma2(ull& d, ull a, ull b) {
    asm("fma.rn.f32x2 %0, %1, %2, %0;" : "+l"(d) : "l"(a), "l"(b));
}
union U2F2 { ull u; float2 f; };

// ---------------------------------------------------------------------------
// Kernel 1: per (b,v) strength category + dominant lag -> combo index.
// ---------------------------------------------------------------------------
__global__ __launch_bounds__(96) void reduce_kernel(const float* __restrict__ cm) {
    __shared__ float sh_s[V_ * L1_];
    __shared__ float sh_a[V_ * L1_];
    const int b = blockIdx.x;
    const int t = threadIdx.x;                  // 0..95
    const float4* p = (const float4*)(cm + (size_t)b * (V_ * V_ * L1_)) + t;
    float4 s = make_float4(0.f, 0.f, 0.f, 0.f);
    float4 a = make_float4(0.f, 0.f, 0.f, 0.f);
#pragma unroll 8
    for (int c = 0; c < V_; ++c) {
        float4 x = __ldcs(&p[c * 96]);          // streamed once: evict-first
        s.x += x.x; s.y += x.y; s.z += x.z; s.w += x.w;
        a.x += fabsf(x.x); a.y += fabsf(x.y); a.z += fabsf(x.z); a.w += fabsf(x.w);
    }
    sh_s[4 * t + 0] = s.x; sh_s[4 * t + 1] = s.y; sh_s[4 * t + 2] = s.z; sh_s[4 * t + 3] = s.w;
    sh_a[4 * t + 0] = a.x; sh_a[4 * t + 1] = a.y; sh_a[4 * t + 2] = a.z; sh_a[4 * t + 3] = a.w;
    __syncthreads();
    if (t < V_) {                               // t = v
        const int base = t * L1_;
        float tot  = sh_s[base];
        float best = sh_a[base];
        int   bl   = 0;
#pragma unroll
        for (int l = 1; l < L1_; ++l) {
            tot += sh_s[base + l];
            float av = sh_a[base + l];
            if (av > best) { best = av; bl = l; }    // first-max (jnp.argmax)
        }
        float mean = tot * (1.0f / (float)(V_ * L1_));
        int cat = (mean > 0.1f) ? 1 : ((mean < -0.1f) ? 2 : 0);
        g_idx[b * V_ + t] = t * 18 + cat * 6 + bl;
    }
}

// ---------------------------------------------------------------------------
// Kernel 2: embedding partial GEMM, k-split by KCH=8 (k chunks of 64).
// ---------------------------------------------------------------------------
__global__ __launch_bounds__(D_) void emb_gemm_kernel(
    const float* __restrict__ vt, const float* __restrict__ st,
    const float* __restrict__ lt, const float* __restrict__ W1) {
    const int g  = blockIdx.x;   // 0..18 row group
    const int kc = blockIdx.y;   // 0..KCH-1 k chunk
    const int d  = threadIdx.x;

    int r0g, nrows, koff;
    const float* src;
    if (g < 16)       { nrows = 4;                 koff = 0;      r0g = g * 4;          src = vt + g * 4 * D_; }
    else if (g == 16) { nrows = 3;                 koff = D_;     r0g = 64;             src = st; }
    else              { int o = (g - 17) * 4;
                        nrows = (6 - o < 4) ? (6 - o) : 4;
                        koff = 2 * D_;             r0g = 67 + o;  src = lt + o * D_; }

    __shared__ float se[4 * D_];
    for (int r = 0; r < nrows; ++r) se[r * D_ + d] = src[r * D_ + d];
    for (int r = nrows; r < 4; ++r) se[r * D_ + d] = 0.f;
    __syncthreads();

    const int k0 = kc * (D_ / KCH);
    float acc[4] = {0.f, 0.f, 0.f, 0.f};
    const float* w = W1 + (size_t)(koff + k0) * D_ + d;
#pragma unroll 8
    for (int k = 0; k < D_ / KCH; ++k) {
        float wv = w[(size_t)k * D_];
#pragma unroll
        for (int r = 0; r < 4; ++r) acc[r] = fmaf(se[r * D_ + k0 + k], wv, acc[r]);
    }
    for (int r = 0; r < nrows; ++r)
        g_rowsP[(size_t)(kc * NEMB + r0g + r) * D_ + d] = acc[r];
}

// ---------------------------------------------------------------------------
// Kernel 3 (v2): g_Tpre[r] = relu( sum_kc partials + b1 ), float4 per thread.
// 1152 blocks x 128 threads.
// ---------------------------------------------------------------------------
__global__ __launch_bounds__(128) void tpre_kernel(const float* __restrict__ b1) {
    const int r  = blockIdx.x;
    const int d4 = threadIdx.x;                 // float4 index 0..127
    const int v = r / 18, rem = r % 18, c = rem / 6, l = rem % 6;
    float4 x = *(const float4*)(b1 + d4 * 4);
#pragma unroll
    for (int kc = 0; kc < KCH; ++kc) {
        const float4* base = (const float4*)(g_rowsP + (size_t)kc * NEMB * D_);
        float4 pv = base[v * 128 + d4];
        float4 pc = base[(64 + c) * 128 + d4];
        float4 pl = base[(67 + l) * 128 + d4];
        x.x += pv.x + pc.x + pl.x;
        x.y += pv.y + pc.y + pl.y;
        x.z += pv.z + pc.z + pl.z;
        x.w += pv.w + pc.w + pl.w;
    }
    x.x = fmaxf(x.x, 0.f); x.y = fmaxf(x.y, 0.f);
    x.z = fmaxf(x.z, 0.f); x.w = fmaxf(x.w, 0.f);
    *(float4*)&g_Tpre[(size_t)r * D_ + d4 * 4] = x;
}

// ---------------------------------------------------------------------------
// Kernel 4: g_Tp[z] = g_Tpre(1152x512) @ W2[kz quarter], k-split by 4.
// BM=64, BN=64, BK=16, 128 threads, 8x4 micro via FFMA2 (fma.rn.f32x2):
// acc packed along m (pairs contiguous in k-major As); Bs stored pre-duplicated
// as (b,b) pairs -> inner kk: 2 LDS(a) + 2 LDS(b) + 16 FFMA2 (vs 35 scalar).
// grid (18, 8, 4) = 576 CTAs; reg-prefetch double buffer.
// ---------------------------------------------------------------------------
#define BM 64
#define BN 64
#define BK 16
#define NKB (D_ / (BK * KSP))   // 8 k-blocks per CTA
#define APAD 68                 // As row stride (floats), 272B = 16B-aligned
#define BN2 (BN * 2)            // duplicated B row (floats)
__global__ __launch_bounds__(128) void gemm_T_kernel(const float* __restrict__ W2) {
    __shared__ float As[2][BK][APAD];   // k-major A tile
    __shared__ float Bs2[2][BK][BN2];   // B tile, each value duplicated (b,b)
    const int bm  = blockIdx.x;   // 0..17
    const int bn  = blockIdx.y;   // 0..7
    const int kz  = blockIdx.z;   // 0..3
    const int tid = threadIdx.x;
    const int tx  = tid & 15;     // n micro (4 cols)
    const int ty  = tid >> 4;     // m micro (8 rows = 4 pairs)

    const int kbase = kz * (D_ / KSP);

    const int a_m = tid >> 2;          // 0..31 (and +32)
    const int a_k = (tid & 3) * 4;     // 0,4,8,12
    const int b_k = tid >> 4;          // 0..7
    const int b_n = (tid & 15) * 4;    // 0..60

    const float* Aptr = g_Tpre + (size_t)(bm * BM) * D_ + kbase;
    const float* Bptr = W2 + (size_t)kbase * D_ + bn * BN;

    ull acc2[4][4];                    // [m-pair][n], each = (acc[2i], acc[2i+1])
#pragma unroll
    for (int i = 0; i < 4; ++i)
#pragma unroll
        for (int j = 0; j < 4; ++j) acc2[i][j] = 0ull;

    float4 pa0, pa1, pb0, pb1;

    // prologue: fetch k-block 0
    pa0 = *(const float4*)(Aptr + (size_t)a_m        * D_ + a_k);
    pa1 = *(const float4*)(Aptr + (size_t)(a_m + 32) * D_ + a_k);
    pb0 = *(const float4*)(Bptr + (size_t)(b_k + 0) * D_ + b_n);
    pb1 = *(const float4*)(Bptr + (size_t)(b_k + 8) * D_ + b_n);
    {
        As[0][a_k + 0][a_m] = pa0.x; As[0][a_k + 1][a_m] = pa0.y;
        As[0][a_k + 2][a_m] = pa0.z; As[0][a_k + 3][a_m] = pa0.w;
        As[0][a_k + 0][a_m + 32] = pa1.x; As[0][a_k + 1][a_m + 32] = pa1.y;
        As[0][a_k + 2][a_m + 32] = pa1.z; As[0][a_k + 3][a_m + 32] = pa1.w;
        *(float4*)&Bs2[0][b_k + 0][b_n * 2]     = make_float4(pb0.x, pb0.x, pb0.y, pb0.y);
        *(float4*)&Bs2[0][b_k + 0][b_n * 2 + 4] = make_float4(pb0.z, pb0.z, pb0.w, pb0.w);
        *(float4*)&Bs2[0][b_k + 8][b_n * 2]     = make_float4(pb1.x, pb1.x, pb1.y, pb1.y);
        *(float4*)&Bs2[0][b_k + 8][b_n * 2 + 4] = make_float4(pb1.z, pb1.z, pb1.w, pb1.w);
    }
    __syncthreads();

#pragma unroll 1
    for (int kb = 0; kb < NKB; ++kb) {
        const int cur = kb & 1;
        if (kb + 1 < NKB) {
            const int k0 = (kb + 1) * BK;
            pa0 = *(const float4*)(Aptr + (size_t)a_m        * D_ + k0 + a_k);
            pa1 = *(const float4*)(Aptr + (size_t)(a_m + 32) * D_ + k0 + a_k);
            pb0 = *(const float4*)(Bptr + (size_t)(k0 + b_k + 0) * D_ + b_n);
            pb1 = *(const float4*)(Bptr + (size_t)(k0 + b_k + 8) * D_ + b_n);
        }
#pragma unroll
        for (int kk = 0; kk < BK; ++kk) {
            const ull* au = (const ull*)&As[cur][kk][ty * 8];      // 4 m-pairs
            const ull* bu = (const ull*)&Bs2[cur][kk][tx * 8];     // 4 (b,b)
            ull a0 = au[0], a1 = au[1], a2 = au[2], a3 = au[3];
            ull b0 = bu[0], b1 = bu[1], b2 = bu[2], b3 = bu[3];
            ffma2(acc2[0][0], a0, b0); ffma2(acc2[0][1], a0, b1);
            ffma2(acc2[0][2], a0, b2); ffma2(acc2[0][3], a0, b3);
            ffma2(acc2[1][0], a1, b0); ffma2(acc2[1][1], a1, b1);
            ffma2(acc2[1][2], a1, b2); ffma2(acc2[1][3], a1, b3);
            ffma2(acc2[2][0], a2, b0); ffma2(acc2[2][1], a2, b1);
            ffma2(acc2[2][2], a2, b2); ffma2(acc2[2][3], a2, b3);
            ffma2(acc2[3][0], a3, b0); ffma2(acc2[3][1], a3, b1);
            ffma2(acc2[3][2], a3, b2); ffma2(acc2[3][3], a3, b3);
        }
        if (kb + 1 < NKB) {
            const int nxt = cur ^ 1;
            As[nxt][a_k + 0][a_m] = pa0.x; As[nxt][a_k + 1][a_m] = pa0.y;
            As[nxt][a_k + 2][a_m] = pa0.z; As[nxt][a_k + 3][a_m] = pa0.w;
            As[nxt][a_k + 0][a_m + 32] = pa1.x; As[nxt][a_k + 1][a_m + 32] = pa1.y;
            As[nxt][a_k + 2][a_m + 32] = pa1.z; As[nxt][a_k + 3][a_m + 32] = pa1.w;
            *(float4*)&Bs2[nxt][b_k + 0][b_n * 2]     = make_float4(pb0.x, pb0.x, pb0.y, pb0.y);
            *(float4*)&Bs2[nxt][b_k + 0][b_n * 2 + 4] = make_float4(pb0.z, pb0.z, pb0.w, pb0.w);
            *(float4*)&Bs2[nxt][b_k + 8][b_n * 2]     = make_float4(pb1.x, pb1.x, pb1.y, pb1.y);
            *(float4*)&Bs2[nxt][b_k + 8][b_n * 2 + 4] = make_float4(pb1.z, pb1.z, pb1.w, pb1.w);
            __syncthreads();
        }
    }

    float* Tout = g_Tp + (size_t)kz * NROWS * D_;
    const int m0 = bm * BM + ty * 8;
    const int n0 = bn * BN + tx * 4;
#pragma unroll
    for (int i2 = 0; i2 < 4; ++i2) {
        U2F2 c0, c1, c2, c3;
        c0.u = acc2[i2][0]; c1.u = acc2[i2][1];
        c2.u = acc2[i2][2]; c3.u = acc2[i2][3];
        float4 e0 = make_float4(c0.f.x, c1.f.x, c2.f.x, c3.f.x);
        float4 e1 = make_float4(c0.f.y, c1.f.y, c2.f.y, c3.f.y);
        *(float4*)&Tout[(size_t)(m0 + 2 * i2)     * D_ + n0] = e0;
        *(float4*)&Tout[(size_t)(m0 + 2 * i2 + 1) * D_ + n0] = e1;
    }
}

// ---------------------------------------------------------------------------
// Kernel 4b: g_T = sum_z g_Tp[z] + b2  (L2-resident)
// ---------------------------------------------------------------------------
__global__ __launch_bounds__(256) void combine_kernel(const float* __restrict__ b2) {
    const int i = blockIdx.x * 256 + threadIdx.x;     // float4 index
    const int d4 = i & 127;                           // float4 within row
    float4 bb = *(const float4*)(b2 + d4 * 4);
    float4 o = bb;
#pragma unroll
    for (int z = 0; z < KSP; ++z) {
        float4 p = *(const float4*)&g_Tp[((size_t)z * NROWS * (D_ / 4) + i) * 4];
        o.x += p.x; o.y += p.y; o.z += p.z; o.w += p.w;
    }
    *(float4*)&g_T[(size_t)i * 4] = o;
}

// ---------------------------------------------------------------------------
// Kernel 5: out[row] = g_T[idx[row]] with intra-block row reuse (round-13).
// ---------------------------------------------------------------------------
__global__ __launch_bounds__(512) void gather_kernel(float* __restrict__ out) {
    const int v    = blockIdx.x >> 4;                   // 0..63
    const int grp  = blockIdx.x & 15;                   // 0..15 (64 b's each)
    const int sub  = threadIdx.x >> 7;                  // 0..3
    const int lane = threadIdx.x & 127;                 // 128 float4 = 512 floats
#pragma unroll 4
    for (int it = 0; it < 16; ++it) {
        const int b   = grp * 64 + it * 4 + sub;
        const int row = b * V_ + v;
        const int r   = g_idx[row];                     // broadcast per 128 lanes
        const float4* src = (const float4*)(g_T + (size_t)r * D_);
        float4* dst = (float4*)(out + (size_t)row * D_);
        __stcs(&dst[lane], __ldg(&src[lane]));
    }
}

// ---------------------------------------------------------------------------
extern "C" void kernel_launch(void* const* d_in, const int* in_sizes, int n_in,
                              void* d_out, int out_size) {
    const float* cm = (const float*)d_in[0];
    const float* vt = (const float*)d_in[1];
    const float* st = (const float*)d_in[2];
    const float* lt = (const float*)d_in[3];
    const float* W1 = (const float*)d_in[4];
    const float* b1 = (const float*)d_in[5];
    const float* W2 = (const float*)d_in[6];
    const float* b2 = (const float*)d_in[7];
    float* out = (float*)d_out;

    static cudaStream_t s2 = nullptr;
    static cudaEvent_t  evFork = nullptr, evReduce = nullptr;
    if (!s2) {
        cudaStreamCreateWithFlags(&s2, cudaStreamNonBlocking);
        cudaEventCreateWithFlags(&evFork,   cudaEventDisableTiming);
        cudaEventCreateWithFlags(&evReduce, cudaEventDisableTiming);
    }

    // Fork: reduce (independent) on s2, table chain on main stream.
    cudaEventRecord(evFork, 0);
    cudaStreamWaitEvent(s2, evFork, 0);
    reduce_kernel<<<B_, 96, 0, s2>>>(cm);
    cudaEventRecord(evReduce, s2);

    dim3 ge(19, KCH);
    emb_gemm_kernel<<<ge, D_>>>(vt, st, lt, W1);
    tpre_kernel<<<NROWS, 128>>>(b1);
    dim3 gg(NROWS / BM, D_ / BN, KSP);
    gemm_T_kernel<<<gg, 128>>>(W2);
    combine_kernel<<<(NROWS * D_ / 4) / 256, 256>>>(b2);

    // Join: gather needs both the table (main stream) and idx (s2).
    cudaStreamWaitEvent(0, evReduce, 0);
    gather_kernel<<<V_ * 16, 512>>>(out);
}

// round 15
// speedup vs baseline: 1.1719x; 1.1719x over previous
#include <cuda_runtime.h>
#include <math.h>

#define B_    1024
#define V_    64
#define L1_   6
#define D_    512
#define NROWS 1152   // V * 3 * 6 distinct (var, cat, lag) combos
#define NEMB  73     // 64 var + 3 strength + 6 lag partial-GEMM rows
#define KCH   8      // k-split chunks for the embedding GEMM
#define KSP   8      // k-split for the table GEMM (per row half)
#define HROWS (NROWS / 2)   // 576 rows per half (v 0..31 / 32..63)

// Static scratch (no allocations allowed)
__device__ float g_rowsP[KCH * NEMB * D_];  // k-split partials of emb @ W1
__device__ float g_Tpre[NROWS * D_];        // relu(...) rows
__device__ float g_Tp[KSP * NROWS * D_];    // table GEMM k-partials (18.9 MB)
__device__ float g_T[NROWS * D_];           // final row table
__device__ int   g_idx[B_ * V_];            // per (b,v) combo index

// ---------------------------------------------------------------------------
// Kernel 1: per (b,v) strength category + dominant lag -> combo index.
// ---------------------------------------------------------------------------
__global__ __launch_bounds__(96) void reduce_kernel(const float* __restrict__ cm) {
    __shared__ float sh_s[V_ * L1_];
    __shared__ float sh_a[V_ * L1_];
    const int b = blockIdx.x;
    const int t = threadIdx.x;                  // 0..95
    const float4* p = (const float4*)(cm + (size_t)b * (V_ * V_ * L1_)) + t;
    float4 s = make_float4(0.f, 0.f, 0.f, 0.f);
    float4 a = make_float4(0.f, 0.f, 0.f, 0.f);
#pragma unroll 8
    for (int c = 0; c < V_; ++c) {
        float4 x = __ldcs(&p[c * 96]);          // streamed once: evict-first
        s.x += x.x; s.y += x.y; s.z += x.z; s.w += x.w;
        a.x += fabsf(x.x); a.y += fabsf(x.y); a.z += fabsf(x.z); a.w += fabsf(x.w);
    }
    sh_s[4 * t + 0] = s.x; sh_s[4 * t + 1] = s.y; sh_s[4 * t + 2] = s.z; sh_s[4 * t + 3] = s.w;
    sh_a[4 * t + 0] = a.x; sh_a[4 * t + 1] = a.y; sh_a[4 * t + 2] = a.z; sh_a[4 * t + 3] = a.w;
    __syncthreads();
    if (t < V_) {                               // t = v
        const int base = t * L1_;
        float tot  = sh_s[base];
        float best = sh_a[base];
        int   bl   = 0;
#pragma unroll
        for (int l = 1; l < L1_; ++l) {
            tot += sh_s[base + l];
            float av = sh_a[base + l];
            if (av > best) { best = av; bl = l; }    // first-max (jnp.argmax)
        }
        float mean = tot * (1.0f / (float)(V_ * L1_));
        int cat = (mean > 0.1f) ? 1 : ((mean < -0.1f) ? 2 : 0);
        g_idx[b * V_ + t] = t * 18 + cat * 6 + bl;
    }
}

// ---------------------------------------------------------------------------
// Kernel 2: embedding partial GEMM, k-split by KCH=8 (k chunks of 64).
// ---------------------------------------------------------------------------
__global__ __launch_bounds__(D_) void emb_gemm_kernel(
    const float* __restrict__ vt, const float* __restrict__ st,
    const float* __restrict__ lt, const float* __restrict__ W1) {
    const int g  = blockIdx.x;   // 0..18 row group
    const int kc = blockIdx.y;   // 0..KCH-1 k chunk
    const int d  = threadIdx.x;

    int r0g, nrows, koff;
    const float* src;
    if (g < 16)       { nrows = 4;                 koff = 0;      r0g = g * 4;          src = vt + g * 4 * D_; }
    else if (g == 16) { nrows = 3;                 koff = D_;     r0g = 64;             src = st; }
    else              { int o = (g - 17) * 4;
                        nrows = (6 - o < 4) ? (6 - o) : 4;
                        koff = 2 * D_;             r0g = 67 + o;  src = lt + o * D_; }

    __shared__ float se[4 * D_];
    for (int r = 0; r < nrows; ++r) se[r * D_ + d] = src[r * D_ + d];
    for (int r = nrows; r < 4; ++r) se[r * D_ + d] = 0.f;
    __syncthreads();

    const int k0 = kc * (D_ / KCH);
    float acc[4] = {0.f, 0.f, 0.f, 0.f};
    const float* w = W1 + (size_t)(koff + k0) * D_ + d;
#pragma unroll 8
    for (int k = 0; k < D_ / KCH; ++k) {
        float wv = w[(size_t)k * D_];
#pragma unroll
        for (int r = 0; r < 4; ++r) acc[r] = fmaf(se[r * D_ + k0 + k], wv, acc[r]);
    }
    for (int r = 0; r < nrows; ++r)
        g_rowsP[(size_t)(kc * NEMB + r0g + r) * D_ + d] = acc[r];
}

// ---------------------------------------------------------------------------
// Kernel 3 (v2): g_Tpre[r] = relu( sum_kc partials + b1 ), float4 per thread.
// ---------------------------------------------------------------------------
__global__ __launch_bounds__(128) void tpre_kernel(const float* __restrict__ b1) {
    const int r  = blockIdx.x;
    const int d4 = threadIdx.x;                 // float4 index 0..127
    const int v = r / 18, rem = r % 18, c = rem / 6, l = rem % 6;
    float4 x = *(const float4*)(b1 + d4 * 4);
#pragma unroll
    for (int kc = 0; kc < KCH; ++kc) {
        const float4* base = (const float4*)(g_rowsP + (size_t)kc * NEMB * D_);
        float4 pv = base[v * 128 + d4];
        float4 pc = base[(64 + c) * 128 + d4];
        float4 pl = base[(67 + l) * 128 + d4];
        x.x += pv.x + pc.x + pl.x;
        x.y += pv.y + pc.y + pl.y;
        x.z += pv.z + pc.z + pl.z;
        x.w += pv.w + pc.w + pl.w;
    }
    x.x = fmaxf(x.x, 0.f); x.y = fmaxf(x.y, 0.f);
    x.z = fmaxf(x.z, 0.f); x.w = fmaxf(x.w, 0.f);
    *(float4*)&g_Tpre[(size_t)r * D_ + d4 * 4] = x;
}

// ---------------------------------------------------------------------------
// Kernel 4: table GEMM, one ROW half (576 rows), k-split by KSP=8.
// BM=64, BN=64, BK=16, 128 threads, 8x4 micro, reg-prefetch double buffer.
// grid per half: (9, 8, 8) = 576 CTAs (shape measured 12.35us in round 8).
// ---------------------------------------------------------------------------
#define BM 64
#define BN 64
#define BK 16
#define NKB (D_ / (BK * KSP))   // 4 k-blocks per CTA
#define APAD 68
__global__ __launch_bounds__(128) void gemm_T_kernel(const float* __restrict__ W2,
                                                     int m_off) {
    __shared__ float As[2][BK][APAD];  // k-major A tile (padded)
    __shared__ float Bs[2][BK][BN];
    const int bm  = blockIdx.x;   // 0..8
    const int bn  = blockIdx.y;   // 0..7
    const int kz  = blockIdx.z;   // 0..7
    const int tid = threadIdx.x;
    const int tx  = tid & 15;     // n micro (4 cols)
    const int ty  = tid >> 4;     // m micro (8 rows)

    const int kbase = kz * (D_ / KSP);          // multiples of 64
    const int mbase = m_off + bm * BM;

    const int a_m = tid >> 2;          // 0..31 (and +32)
    const int a_k = (tid & 3) * 4;     // 0,4,8,12
    const int b_k = tid >> 4;          // 0..7
    const int b_n = (tid & 15) * 4;    // 0..60

    const float* Aptr = g_Tpre + (size_t)mbase * D_ + kbase;
    const float* Bptr = W2 + (size_t)kbase * D_ + bn * BN;

    float acc[8][4] = {};
    float4 pa0, pa1, pb0, pb1;

    pa0 = *(const float4*)(Aptr + (size_t)a_m        * D_ + a_k);
    pa1 = *(const float4*)(Aptr + (size_t)(a_m + 32) * D_ + a_k);
    pb0 = *(const float4*)(Bptr + (size_t)(b_k + 0) * D_ + b_n);
    pb1 = *(const float4*)(Bptr + (size_t)(b_k + 8) * D_ + b_n);
    {
        As[0][a_k + 0][a_m] = pa0.x; As[0][a_k + 1][a_m] = pa0.y;
        As[0][a_k + 2][a_m] = pa0.z; As[0][a_k + 3][a_m] = pa0.w;
        As[0][a_k + 0][a_m + 32] = pa1.x; As[0][a_k + 1][a_m + 32] = pa1.y;
        As[0][a_k + 2][a_m + 32] = pa1.z; As[0][a_k + 3][a_m + 32] = pa1.w;
        *(float4*)&Bs[0][b_k + 0][b_n] = pb0;
        *(float4*)&Bs[0][b_k + 8][b_n] = pb1;
    }
    __syncthreads();

#pragma unroll 1
    for (int kb = 0; kb < NKB; ++kb) {
        const int cur = kb & 1;
        if (kb + 1 < NKB) {
            const int k0 = (kb + 1) * BK;
            pa0 = *(const float4*)(Aptr + (size_t)a_m        * D_ + k0 + a_k);
            pa1 = *(const float4*)(Aptr + (size_t)(a_m + 32) * D_ + k0 + a_k);
            pb0 = *(const float4*)(Bptr + (size_t)(k0 + b_k + 0) * D_ + b_n);
            pb1 = *(const float4*)(Bptr + (size_t)(k0 + b_k + 8) * D_ + b_n);
        }
#pragma unroll
        for (int kk = 0; kk < BK; ++kk) {
            float4 a0 = *(const float4*)&As[cur][kk][ty * 8];
            float4 a1 = *(const float4*)&As[cur][kk][ty * 8 + 4];
            float4 bv = *(const float4*)&Bs[cur][kk][tx * 4];
            float arr[8] = {a0.x, a0.y, a0.z, a0.w, a1.x, a1.y, a1.z, a1.w};
            float brr[4] = {bv.x, bv.y, bv.z, bv.w};
#pragma unroll
            for (int i = 0; i < 8; ++i)
#pragma unroll
                for (int j = 0; j < 4; ++j)
                    acc[i][j] = fmaf(arr[i], brr[j], acc[i][j]);
        }
        if (kb + 1 < NKB) {
            const int nxt = cur ^ 1;
            As[nxt][a_k + 0][a_m] = pa0.x; As[nxt][a_k + 1][a_m] = pa0.y;
            As[nxt][a_k + 2][a_m] = pa0.z; As[nxt][a_k + 3][a_m] = pa0.w;
            As[nxt][a_k + 0][a_m + 32] = pa1.x; As[nxt][a_k + 1][a_m + 32] = pa1.y;
            As[nxt][a_k + 2][a_m + 32] = pa1.z; As[nxt][a_k + 3][a_m + 32] = pa1.w;
            *(float4*)&Bs[nxt][b_k + 0][b_n] = pb0;
            *(float4*)&Bs[nxt][b_k + 8][b_n] = pb1;
            __syncthreads();
        }
    }

    float* Tout = g_Tp + (size_t)kz * NROWS * D_;
    const int m0 = mbase + ty * 8;
    const int n0 = bn * BN + tx * 4;
#pragma unroll
    for (int i = 0; i < 8; ++i) {
        float4 o;
        o.x = acc[i][0]; o.y = acc[i][1]; o.z = acc[i][2]; o.w = acc[i][3];
        *(float4*)&Tout[(size_t)(m0 + i) * D_ + n0] = o;
    }
}

// ---------------------------------------------------------------------------
// Kernel 4b: g_T[half rows] = sum_z g_Tp[z] + b2  (L2-resident)
// ---------------------------------------------------------------------------
__global__ __launch_bounds__(256) void combine_kernel(const float* __restrict__ b2,
                                                      int half) {
    const size_t off = (size_t)half * HROWS * (D_ / 4)
                     + blockIdx.x * 256 + threadIdx.x;   // global float4 index
    const int d4 = (int)(off & 127);                     // float4 within row
    float4 bb = *(const float4*)(b2 + d4 * 4);
    float4 o = bb;
#pragma unroll
    for (int z = 0; z < KSP; ++z) {
        float4 p = *(const float4*)&g_Tp[((size_t)z * NROWS * (D_ / 4) + off) * 4];
        o.x += p.x; o.y += p.y; o.z += p.z; o.w += p.w;
    }
    *(float4*)&g_T[off * 4] = o;
}

// ---------------------------------------------------------------------------
// Kernel 5: out[row] = g_T[idx[row]] for one v-half, intra-block row reuse.
// Block = (v, 64-batch range); 512 blocks per half.
// ---------------------------------------------------------------------------
__global__ __launch_bounds__(512) void gather_kernel(float* __restrict__ out,
                                                     int vbase) {
    const int v    = vbase + (blockIdx.x >> 4);         // half of 0..63
    const int grp  = blockIdx.x & 15;                   // 0..15 (64 b's each)
    const int sub  = threadIdx.x >> 7;                  // 0..3
    const int lane = threadIdx.x & 127;                 // 128 float4 = 512 floats
#pragma unroll 4
    for (int it = 0; it < 16; ++it) {
        const int b   = grp * 64 + it * 4 + sub;
        const int row = b * V_ + v;
        const int r   = g_idx[row];                     // broadcast per 128 lanes
        const float4* src = (const float4*)(g_T + (size_t)r * D_);
        float4* dst = (float4*)(out + (size_t)row * D_);
        __stcs(&dst[lane], __ldg(&src[lane]));
    }
}

// ---------------------------------------------------------------------------
extern "C" void kernel_launch(void* const* d_in, const int* in_sizes, int n_in,
                              void* d_out, int out_size) {
    const float* cm = (const float*)d_in[0];
    const float* vt = (const float*)d_in[1];
    const float* st = (const float*)d_in[2];
    const float* lt = (const float*)d_in[3];
    const float* W1 = (const float*)d_in[4];
    const float* b1 = (const float*)d_in[5];
    const float* W2 = (const float*)d_in[6];
    const float* b2 = (const float*)d_in[7];
    float* out = (float*)d_out;

    static cudaStream_t s2 = nullptr, s3 = nullptr;
    static cudaEvent_t evFork = nullptr, evReduce = nullptr, evA = nullptr, evGA = nullptr;
    if (!s2) {
        cudaStreamCreateWithFlags(&s2, cudaStreamNonBlocking);
        cudaStreamCreateWithFlags(&s3, cudaStreamNonBlocking);
        cudaEventCreateWithFlags(&evFork,   cudaEventDisableTiming);
        cudaEventCreateWithFlags(&evReduce, cudaEventDisableTiming);
        cudaEventCreateWithFlags(&evA,      cudaEventDisableTiming);
        cudaEventCreateWithFlags(&evGA,     cudaEventDisableTiming);
    }

    // Fork: reduce (independent) on s2, table chain on main stream.
    cudaEventRecord(evFork, 0);
    cudaStreamWaitEvent(s2, evFork, 0);
    reduce_kernel<<<B_, 96, 0, s2>>>(cm);
    cudaEventRecord(evReduce, s2);

    dim3 ge(19, KCH);
    emb_gemm_kernel<<<ge, D_>>>(vt, st, lt, W1);
    tpre_kernel<<<NROWS, 128>>>(b1);

    dim3 gg(HROWS / BM, D_ / BN, KSP);                  // (9, 8, 8)
    const int comb_blocks = (HROWS * D_ / 4) / 256;     // 288

    // Half A: table rows 0..575 (v 0..31). Gather A forked to s3,
    // overlapping half-B gemm (disjoint resources: DRAM-write vs FMA).
    gemm_T_kernel<<<gg, 128>>>(W2, 0);
    combine_kernel<<<comb_blocks, 256>>>(b2, 0);
    cudaEventRecord(evA, 0);
    cudaStreamWaitEvent(s3, evA, 0);
    cudaStreamWaitEvent(s3, evReduce, 0);
    gather_kernel<<<512, 512, 0, s3>>>(out, 0);
    cudaEventRecord(evGA, s3);

    // Half B: table rows 576..1151 (v 32..63) on main.
    gemm_T_kernel<<<gg, 128>>>(W2, HROWS);
    combine_kernel<<<comb_blocks, 256>>>(b2, 1);
    cudaStreamWaitEvent(0, evReduce, 0);
    gather_kernel<<<512, 512>>>(out, 32);

    // Join s3 back into the main stream.
    cudaStreamWaitEvent(0, evGA, 0);
}